// round 1
// baseline (speedup 1.0000x reference)
#include <cuda_runtime.h>
#include <math_constants.h>

#define BB 256
#define TT 16
#define SS 32
#define DD 768
#define DD4 192
#define SPLITK 4

// ---- scratch (static device globals; no allocation) ----
__device__ float d_vq[BB * DD];
__device__ float d_tlm[BB * DD];
__device__ float d_Gp[SPLITK][BB * BB];
__device__ float d_Lp[SPLITK][BB * BB];
__device__ float d_G[BB * BB];
__device__ float d_L[BB * BB];
__device__ float d_lse[3 * BB];

__device__ __forceinline__ float dot4(float4 a, float4 b) {
    return a.x * b.x + a.y * b.y + a.z * b.z + a.w * b.w;
}

// ============================================================================
// K1: per-batch-element b:
//   sim[t][s] = VL[b,t] . TL[b,s]      (16 x 32 dots over D=768)
//   rmax[t]   = max_s sim[t][s]
//   tw        = softmax_t(scale * rmax)
//   vq[b]     = sum_t tw[t] * VL[b,t]
//   tlm[b]    = mean_s TL[b,s]
// Layout: 8 warps; warp w owns s in [4w, 4w+4). Lane = (t = lane&15, h = lane>>4),
// handles s0 = 4w+2h and s0+1. Every TL element is read by exactly one warp
// (broadcast within 16 lanes); VL rows are L1-resident after first warp.
// ============================================================================
__global__ void __launch_bounds__(256) k1_kernel(const float* __restrict__ VL,
                                                 const float* __restrict__ TL,
                                                 const float* __restrict__ temp) {
    int b = blockIdx.x;
    int tid = threadIdx.x, w = tid >> 5, lane = tid & 31;
    int t = lane & 15, h = lane >> 4;
    int s0 = w * 4 + h * 2;

    const float4* vl4 = (const float4*)(VL + (size_t)b * TT * DD) + t * DD4;
    const float4* xa4 = (const float4*)(TL + (size_t)b * SS * DD) + s0 * DD4;
    const float4* xb4 = xa4 + DD4;

    float accA = 0.f, accB = 0.f;
#pragma unroll 4
    for (int k = 0; k < DD4; k++) {
        float4 a = __ldg(vl4 + k);
        float4 p = __ldg(xa4 + k);
        float4 q = __ldg(xb4 + k);
        accA += dot4(a, p);
        accB += dot4(a, q);
    }

    // per-(t, warp) max over this warp's 4 s values
    float m = fmaxf(accA, accB);
    m = fmaxf(m, __shfl_xor_sync(0xffffffffu, m, 16));  // combine h halves

    __shared__ float red[8][16];
    __shared__ float tw[16];
    if (lane < 16) red[w][lane] = m;
    __syncthreads();

    if (w == 0) {
        float scale = expf(__ldg(temp));
        float v = -CUDART_INF_F;
        if (lane < 16) {
            float mm = red[0][lane];
#pragma unroll
            for (int ww = 1; ww < 8; ww++) mm = fmaxf(mm, red[ww][lane]);
            v = mm * scale;
        }
        float mx = v;
#pragma unroll
        for (int o = 16; o; o >>= 1) mx = fmaxf(mx, __shfl_xor_sync(0xffffffffu, mx, o));
        float e = (lane < 16) ? expf(v - mx) : 0.f;
        float ssum = e;
#pragma unroll
        for (int o = 16; o; o >>= 1) ssum += __shfl_xor_sync(0xffffffffu, ssum, o);
        if (lane < 16) tw[lane] = e / ssum;
    }
    __syncthreads();

    // vq and tl_mean: 768 dims / 256 threads = 3 dims per thread (coalesced, L1-hot)
    const float* VLb = VL + (size_t)b * TT * DD;
    const float* TLb = TL + (size_t)b * SS * DD;
#pragma unroll
    for (int j = 0; j < 3; j++) {
        int d = tid + j * 256;
        float a = 0.f;
#pragma unroll
        for (int t2 = 0; t2 < TT; t2++) a += tw[t2] * __ldg(VLb + t2 * DD + d);
        d_vq[b * DD + d] = a;
        float mz = 0.f;
#pragma unroll
        for (int s2 = 0; s2 < SS; s2++) mz += __ldg(TLb + s2 * DD + d);
        d_tlm[b * DD + d] = mz * (1.f / 32.f);
    }
}

// ============================================================================
// GEMM: C = A @ B^T for 256x256x768, both operands row-major [256][768].
// grid (64 tiles of 32x32, 2 problems, SPLITK), block 64 threads.
// Each thread computes a 4x4 micro-tile; shared staging [row][32 k-chunk],
// coalesced global loads, conflict-free STS.128, LDS.128 frag loads.
// Deterministic: each split writes its own partial buffer (summed later).
// ============================================================================
__global__ void __launch_bounds__(64) gemm_kernel(const float* __restrict__ VG,
                                                  const float* __restrict__ TG) {
    const float *A, *Bm;
    float* C;
    if (blockIdx.y == 0) { A = VG;   Bm = TG;    C = d_Gp[blockIdx.z]; }
    else                 { A = d_vq; Bm = d_tlm; C = d_Lp[blockIdx.z]; }

    int tr = blockIdx.x >> 3, tc = blockIdx.x & 7;
    __shared__ float As[32 * 32], Bs[32 * 32];
    int tid = threadIdx.x;
    int r0 = (tid >> 3) << 2, c0 = (tid & 7) << 2;
    float acc[4][4] = {};

    const int ksub = DD / SPLITK;  // 192
    int kbase = blockIdx.z * ksub;
    const float* Arow = A + (size_t)tr * 32 * DD + kbase;
    const float* Brow = Bm + (size_t)tc * 32 * DD + kbase;

    for (int ks = 0; ks < ksub; ks += 32) {
#pragma unroll
        for (int j = 0; j < 4; j++) {
            int e = tid + 64 * j;          // 0..255
            int row = e >> 3, kq = e & 7;  // coalesced 128B per 8 lanes
            float4 av = *(const float4*)(Arow + row * DD + ks + kq * 4);
            float4 bv = *(const float4*)(Brow + row * DD + ks + kq * 4);
            *(float4*)&As[row * 32 + kq * 4] = av;
            *(float4*)&Bs[row * 32 + kq * 4] = bv;
        }
        __syncthreads();
#pragma unroll
        for (int k4 = 0; k4 < 8; k4++) {
            float4 a0 = *(const float4*)&As[(r0 + 0) * 32 + k4 * 4];
            float4 a1 = *(const float4*)&As[(r0 + 1) * 32 + k4 * 4];
            float4 a2 = *(const float4*)&As[(r0 + 2) * 32 + k4 * 4];
            float4 a3 = *(const float4*)&As[(r0 + 3) * 32 + k4 * 4];
            float4 b0 = *(const float4*)&Bs[(c0 + 0) * 32 + k4 * 4];
            float4 b1 = *(const float4*)&Bs[(c0 + 1) * 32 + k4 * 4];
            float4 b2 = *(const float4*)&Bs[(c0 + 2) * 32 + k4 * 4];
            float4 b3 = *(const float4*)&Bs[(c0 + 3) * 32 + k4 * 4];
            acc[0][0] += dot4(a0, b0); acc[0][1] += dot4(a0, b1);
            acc[0][2] += dot4(a0, b2); acc[0][3] += dot4(a0, b3);
            acc[1][0] += dot4(a1, b0); acc[1][1] += dot4(a1, b1);
            acc[1][2] += dot4(a1, b2); acc[1][3] += dot4(a1, b3);
            acc[2][0] += dot4(a2, b0); acc[2][1] += dot4(a2, b1);
            acc[2][2] += dot4(a2, b2); acc[2][3] += dot4(a2, b3);
            acc[3][0] += dot4(a3, b0); acc[3][1] += dot4(a3, b1);
            acc[3][2] += dot4(a3, b2); acc[3][3] += dot4(a3, b3);
        }
        __syncthreads();
    }
#pragma unroll
    for (int i = 0; i < 4; i++) {
        float4 o = make_float4(acc[i][0], acc[i][1], acc[i][2], acc[i][3]);
        *(float4*)&C[(tr * 32 + r0 + i) * BB + tc * 32 + c0] = o;
    }
}

// ============================================================================
// Sum split-K partials (fixed order -> deterministic) and apply logit scale.
// 65536 floats per matrix -> 16384 float4 -> grid 64 x 256.
// ============================================================================
__global__ void __launch_bounds__(256) reduce_kernel(const float* __restrict__ temp) {
    float scale = expf(__ldg(temp));
    int i = blockIdx.x * 256 + threadIdx.x;  // 0..16383
    float4 g = ((const float4*)d_Gp[0])[i];
    float4 l = ((const float4*)d_Lp[0])[i];
#pragma unroll
    for (int p = 1; p < SPLITK; p++) {
        float4 gp = ((const float4*)d_Gp[p])[i];
        float4 lp = ((const float4*)d_Lp[p])[i];
        g.x += gp.x; g.y += gp.y; g.z += gp.z; g.w += gp.w;
        l.x += lp.x; l.y += lp.y; l.z += lp.z; l.w += lp.w;
    }
    g.x *= scale; g.y *= scale; g.z *= scale; g.w *= scale;
    l.x *= scale; l.y *= scale; l.z *= scale; l.w *= scale;
    ((float4*)d_G)[i] = g;
    ((float4*)d_L)[i] = l;
}

// ============================================================================
// Row/col logsumexp. blocks [0,256): rows of G; [256,512): cols of G;
// [512,768): rows of L. 256 threads, one element per thread.
// ============================================================================
__global__ void __launch_bounds__(256) lse_kernel() {
    int id = blockIdx.x, tid = threadIdx.x;
    float v;
    if (id < 256)      v = d_G[id * BB + tid];
    else if (id < 512) v = d_G[tid * BB + (id - 256)];
    else               v = d_L[(id - 512) * BB + tid];

    __shared__ float sm[8];
    int w = tid >> 5, lane = tid & 31;

    float m = v;
#pragma unroll
    for (int o = 16; o; o >>= 1) m = fmaxf(m, __shfl_xor_sync(0xffffffffu, m, o));
    if (lane == 0) sm[w] = m;
    __syncthreads();
    float mm = sm[0];
#pragma unroll
    for (int i = 1; i < 8; i++) mm = fmaxf(mm, sm[i]);
    __syncthreads();

    float e = expf(v - mm);
#pragma unroll
    for (int o = 16; o; o >>= 1) e += __shfl_xor_sync(0xffffffffu, e, o);
    if (lane == 0) sm[w] = e;
    __syncthreads();
    if (tid == 0) {
        float s = 0.f;
#pragma unroll
        for (int i = 0; i < 8; i++) s += sm[i];
        d_lse[id] = mm + logf(s);
    }
}

// ============================================================================
// Final: loss = 0.6*0.5*(v2t + t2v) + 0.4*local, each a mean over b of
// (lse - diag). One block, 256 threads.
// ============================================================================
__global__ void __launch_bounds__(256) final_kernel(float* __restrict__ out) {
    int tid = threadIdx.x;
    float g = d_G[tid * BB + tid];
    float l = d_L[tid * BB + tid];
    float sg = (d_lse[tid] - g) + (d_lse[256 + tid] - g);
    float sl = d_lse[512 + tid] - l;

    __shared__ float s1[8], s2[8];
    int w = tid >> 5, lane = tid & 31;
#pragma unroll
    for (int o = 16; o; o >>= 1) {
        sg += __shfl_xor_sync(0xffffffffu, sg, o);
        sl += __shfl_xor_sync(0xffffffffu, sl, o);
    }
    if (lane == 0) { s1[w] = sg; s2[w] = sl; }
    __syncthreads();
    if (tid == 0) {
        float tg = 0.f, tl = 0.f;
#pragma unroll
        for (int i = 0; i < 8; i++) { tg += s1[i]; tl += s2[i]; }
        out[0] = 0.3f * (tg / 256.f) + 0.4f * (tl / 256.f);
    }
}

extern "C" void kernel_launch(void* const* d_in, const int* in_sizes, int n_in,
                              void* d_out, int out_size) {
    const float* vg   = (const float*)d_in[0];  // video_global [256,768]
    const float* tg   = (const float*)d_in[1];  // text_global  [256,768]
    const float* vl   = (const float*)d_in[2];  // video_local  [256,16,768]
    const float* tl   = (const float*)d_in[3];  // text_local   [256,32,768]
    const float* temp = (const float*)d_in[4];  // temp [1]
    float* out = (float*)d_out;

    k1_kernel<<<BB, 256>>>(vl, tl, temp);
    gemm_kernel<<<dim3(64, 2, SPLITK), 64>>>(vg, tg);
    reduce_kernel<<<64, 256>>>(temp);
    lse_kernel<<<768, 256>>>();
    final_kernel<<<1, 256>>>(out);
}

// round 2
// speedup vs baseline: 3.2058x; 3.2058x over previous
#include <cuda_runtime.h>
#include <math_constants.h>

#define BB 256
#define DD 768
#define SPLITK 4

// ---- scratch (static device globals; no allocation) ----
__device__ float d_vq[BB * DD];
__device__ float d_tlm[BB * DD];
__device__ float d_Gp[SPLITK][BB * BB];
__device__ float d_GTp[SPLITK][BB * BB];
__device__ float d_Lp[SPLITK][BB * BB];
__device__ float d_lse[3 * BB];
__device__ float d_diagG[BB];
__device__ float d_diagL[BB];

__device__ __forceinline__ float sel4(float4 v, int e) {
    return e == 0 ? v.x : e == 1 ? v.y : e == 2 ? v.z : v.w;
}

// ============================================================================
// K1 (per b): sim[16][32] = VL_b @ TL_b^T (K=768) via smem-tiled GEMM.
// 128 threads = 4 warps; warp w owns k in [w*192, (w+1)*192). Pitch-33 smem
// rows -> conflict-free scalar LDS; 4x4 interleaved micro-tile per lane.
// tl_mean folded into the B-tile staging. Then tw = softmax_t(scale*rowmax),
// vq[b] = sum_t tw[t]*VL[b,t].
// ============================================================================
__global__ void __launch_bounds__(128) k1_kernel(const float* __restrict__ VL,
                                                 const float* __restrict__ TL,
                                                 const float* __restrict__ temp) {
    __shared__ float As[4][16 * 33];
    __shared__ float Bs[4][32 * 33];
    __shared__ float simb[4][512];
    __shared__ float sims[512];
    __shared__ float redm[16];
    __shared__ float tw[16];

    int b = blockIdx.x;
    int tid = threadIdx.x, w = tid >> 5, lane = tid & 31;
    int koff = w * 192;
    int tr = lane >> 3, tc = lane & 7;  // tr 0..3, tc 0..7

    const float* VLb = VL + (size_t)b * 16 * DD;
    const float* TLb = TL + (size_t)b * 32 * DD;

    float acc[4][4] = {};

    for (int ks = 0; ks < 192; ks += 32) {
        // stage A tile [16][32] -> As[w] (coalesced LDG.128, conflict-free STS)
#pragma unroll
        for (int j = 0; j < 4; j++) {
            int idx = lane + 32 * j;
            int row = idx >> 3, kq = idx & 7;
            float4 v = *(const float4*)(VLb + row * DD + koff + ks + kq * 4);
            float* p = &As[w][row * 33 + kq * 4];
            p[0] = v.x; p[1] = v.y; p[2] = v.z; p[3] = v.w;
        }
        // stage B tile [32][32]
#pragma unroll
        for (int j = 0; j < 8; j++) {
            int idx = lane + 32 * j;
            int row = idx >> 3, kq = idx & 7;
            float4 v = *(const float4*)(TLb + row * DD + koff + ks + kq * 4);
            float* p = &Bs[w][row * 33 + kq * 4];
            p[0] = v.x; p[1] = v.y; p[2] = v.z; p[3] = v.w;
        }
        __syncwarp();
#pragma unroll 16
        for (int k = 0; k < 32; k++) {
            float a0 = As[w][(tr)*33 + k];
            float a1 = As[w][(tr + 4) * 33 + k];
            float a2 = As[w][(tr + 8) * 33 + k];
            float a3 = As[w][(tr + 12) * 33 + k];
            float b0 = Bs[w][(tc)*33 + k];
            float b1 = Bs[w][(tc + 8) * 33 + k];
            float b2 = Bs[w][(tc + 16) * 33 + k];
            float b3 = Bs[w][(tc + 24) * 33 + k];
            acc[0][0] += a0 * b0; acc[0][1] += a0 * b1; acc[0][2] += a0 * b2; acc[0][3] += a0 * b3;
            acc[1][0] += a1 * b0; acc[1][1] += a1 * b1; acc[1][2] += a1 * b2; acc[1][3] += a1 * b3;
            acc[2][0] += a2 * b0; acc[2][1] += a2 * b1; acc[2][2] += a2 * b2; acc[2][3] += a2 * b3;
            acc[3][0] += a3 * b0; acc[3][1] += a3 * b1; acc[3][2] += a3 * b2; acc[3][3] += a3 * b3;
        }
        // fold tl_mean: lane = k column; sum the 32 s-rows (conflict-free)
        float tsum = 0.f;
#pragma unroll
        for (int s = 0; s < 32; s++) tsum += Bs[w][s * 33 + lane];
        d_tlm[b * DD + koff + ks + lane] = tsum * (1.f / 32.f);
        __syncwarp();
    }
#pragma unroll
    for (int i = 0; i < 4; i++)
#pragma unroll
        for (int j = 0; j < 4; j++)
            simb[w][(tr + 4 * i) * 32 + tc + 8 * j] = acc[i][j];
    __syncthreads();

    // reduce 4 k-split partials
#pragma unroll
    for (int r = 0; r < 4; r++) {
        int i = tid + 128 * r;
        sims[i] = simb[0][i] + simb[1][i] + simb[2][i] + simb[3][i];
    }
    __syncthreads();

    // row max: thread (t = tid>>3, g = tid&7) scans s = g, g+8, g+16, g+24
    {
        int t = tid >> 3, g = tid & 7;
        float m = sims[t * 32 + g];
#pragma unroll
        for (int u = 1; u < 4; u++) m = fmaxf(m, sims[t * 32 + g + 8 * u]);
#pragma unroll
        for (int off = 1; off < 8; off <<= 1)
            m = fmaxf(m, __shfl_xor_sync(0xffffffffu, m, off));
        if (g == 0) redm[t] = m;
    }
    __syncthreads();

    if (tid < 32) {
        float scale = expf(__ldg(temp));
        float v = (lane < 16) ? redm[lane] * scale : -CUDART_INF_F;
        float mx = v;
#pragma unroll
        for (int o = 16; o; o >>= 1) mx = fmaxf(mx, __shfl_xor_sync(0xffffffffu, mx, o));
        float e = (lane < 16) ? expf(v - mx) : 0.f;
        float ssum = e;
#pragma unroll
        for (int o = 16; o; o >>= 1) ssum += __shfl_xor_sync(0xffffffffu, ssum, o);
        if (lane < 16) tw[lane] = e / ssum;
    }
    __syncthreads();

    // vq[b][d] = sum_t tw[t]*VL[t][d]  (coalesced; VL is L2-resident)
#pragma unroll
    for (int r = 0; r < 6; r++) {
        int d = tid + 128 * r;
        float a = 0.f;
#pragma unroll
        for (int t2 = 0; t2 < 16; t2++) a += tw[t2] * __ldg(VLb + t2 * DD + d);
        d_vq[b * DD + d] = a;
    }
}

// ============================================================================
// GEMM: C = A @ B^T, 256x256x768. grid (64 tiles 32x32, 2 problems, SPLITK),
// 64 threads, 4x4 interleaved micro-tiles, pitch-33 conflict-free smem.
// Problem 0 also writes transposed partials (for column-LSE of G).
// ============================================================================
__global__ void __launch_bounds__(64) gemm_kernel(const float* __restrict__ VG,
                                                  const float* __restrict__ TG) {
    const float *A, *Bm;
    float *C, *CT = nullptr;
    int z = blockIdx.z;
    if (blockIdx.y == 0) { A = VG;   Bm = TG;    C = d_Gp[z]; CT = d_GTp[z]; }
    else                 { A = d_vq; Bm = d_tlm; C = d_Lp[z]; }

    int row0 = (blockIdx.x >> 3) * 32, col0 = (blockIdx.x & 7) * 32;
    __shared__ float As[32 * 33], Bs[32 * 33];
    int tid = threadIdx.x, tr = tid >> 3, tc = tid & 7;  // tr 0..7, tc 0..7
    float acc[4][4] = {};
    int kbase = z * 192;

    for (int ks = 0; ks < 192; ks += 32) {
#pragma unroll
        for (int j = 0; j < 4; j++) {
            int idx = tid + 64 * j;
            int row = idx >> 3, kq = idx & 7;
            float4 va = *(const float4*)(A + (size_t)(row0 + row) * DD + kbase + ks + kq * 4);
            float4 vb = *(const float4*)(Bm + (size_t)(col0 + row) * DD + kbase + ks + kq * 4);
            float* pa = &As[row * 33 + kq * 4];
            pa[0] = va.x; pa[1] = va.y; pa[2] = va.z; pa[3] = va.w;
            float* pb = &Bs[row * 33 + kq * 4];
            pb[0] = vb.x; pb[1] = vb.y; pb[2] = vb.z; pb[3] = vb.w;
        }
        __syncthreads();
#pragma unroll 16
        for (int k = 0; k < 32; k++) {
            float a0 = As[(tr)*33 + k];
            float a1 = As[(tr + 8) * 33 + k];
            float a2 = As[(tr + 16) * 33 + k];
            float a3 = As[(tr + 24) * 33 + k];
            float b0 = Bs[(tc)*33 + k];
            float b1 = Bs[(tc + 8) * 33 + k];
            float b2 = Bs[(tc + 16) * 33 + k];
            float b3 = Bs[(tc + 24) * 33 + k];
            acc[0][0] += a0 * b0; acc[0][1] += a0 * b1; acc[0][2] += a0 * b2; acc[0][3] += a0 * b3;
            acc[1][0] += a1 * b0; acc[1][1] += a1 * b1; acc[1][2] += a1 * b2; acc[1][3] += a1 * b3;
            acc[2][0] += a2 * b0; acc[2][1] += a2 * b1; acc[2][2] += a2 * b2; acc[2][3] += a2 * b3;
            acc[3][0] += a3 * b0; acc[3][1] += a3 * b1; acc[3][2] += a3 * b2; acc[3][3] += a3 * b3;
        }
        __syncthreads();
    }
#pragma unroll
    for (int i = 0; i < 4; i++)
#pragma unroll
        for (int j = 0; j < 4; j++)
            C[(row0 + tr + 8 * i) * BB + col0 + tc + 8 * j] = acc[i][j];
    if (CT) {
#pragma unroll
        for (int i = 0; i < 4; i++)
#pragma unroll
            for (int j = 0; j < 4; j++)
                CT[(col0 + tc + 8 * j) * BB + row0 + tr + 8 * i] = acc[i][j];
    }
}

// ============================================================================
// Fused partial-sum + scale + logsumexp + diag extract. 768 rows, one warp
// per row (96 blocks x 8 warps). Rows 0-255: G rows; 256-511: G cols (from
// GTp); 512-767: L rows. All reads row-major coalesced.
// ============================================================================
__global__ void __launch_bounds__(256) lse_kernel(const float* __restrict__ temp) {
    int gw = blockIdx.x * 8 + (threadIdx.x >> 5);
    int lane = threadIdx.x & 31;
    int kind = gw >> 8, r = gw & 255;
    float scale = expf(__ldg(temp));

    float4 x0 = make_float4(0.f, 0.f, 0.f, 0.f);
    float4 x1 = make_float4(0.f, 0.f, 0.f, 0.f);
#pragma unroll
    for (int p = 0; p < SPLITK; p++) {
        const float* src = (kind == 0 ? d_Gp[p] : kind == 1 ? d_GTp[p] : d_Lp[p]) + r * BB;
        float4 a = ((const float4*)src)[lane];
        float4 b2 = ((const float4*)src)[lane + 32];
        x0.x += a.x; x0.y += a.y; x0.z += a.z; x0.w += a.w;
        x1.x += b2.x; x1.y += b2.y; x1.z += b2.z; x1.w += b2.w;
    }
    x0.x *= scale; x0.y *= scale; x0.z *= scale; x0.w *= scale;
    x1.x *= scale; x1.y *= scale; x1.z *= scale; x1.w *= scale;

    // diagonal element (col == r)
    {
        int f = r >> 2, e = r & 3;
        if (kind == 0 && f < 32 && lane == f) d_diagG[r] = sel4(x0, e);
        if (kind == 0 && f >= 32 && lane == f - 32) d_diagG[r] = sel4(x1, e);
        if (kind == 2 && f < 32 && lane == f) d_diagL[r] = sel4(x0, e);
        if (kind == 2 && f >= 32 && lane == f - 32) d_diagL[r] = sel4(x1, e);
    }

    float m = fmaxf(fmaxf(fmaxf(x0.x, x0.y), fmaxf(x0.z, x0.w)),
                    fmaxf(fmaxf(x1.x, x1.y), fmaxf(x1.z, x1.w)));
#pragma unroll
    for (int o = 16; o; o >>= 1) m = fmaxf(m, __shfl_xor_sync(0xffffffffu, m, o));
    float s = expf(x0.x - m) + expf(x0.y - m) + expf(x0.z - m) + expf(x0.w - m)
            + expf(x1.x - m) + expf(x1.y - m) + expf(x1.z - m) + expf(x1.w - m);
#pragma unroll
    for (int o = 16; o; o >>= 1) s += __shfl_xor_sync(0xffffffffu, s, o);
    if (lane == 0) d_lse[gw] = m + logf(s);
}

// ============================================================================
// Final combine.
// ============================================================================
__global__ void __launch_bounds__(256) final_kernel(float* __restrict__ out) {
    int tid = threadIdx.x;
    float g = d_diagG[tid];
    float l = d_diagL[tid];
    float sg = (d_lse[tid] - g) + (d_lse[256 + tid] - g);
    float sl = d_lse[512 + tid] - l;

    __shared__ float s1[8], s2[8];
    int w = tid >> 5, lane = tid & 31;
#pragma unroll
    for (int o = 16; o; o >>= 1) {
        sg += __shfl_xor_sync(0xffffffffu, sg, o);
        sl += __shfl_xor_sync(0xffffffffu, sl, o);
    }
    if (lane == 0) { s1[w] = sg; s2[w] = sl; }
    __syncthreads();
    if (tid == 0) {
        float tg = 0.f, tl = 0.f;
#pragma unroll
        for (int i = 0; i < 8; i++) { tg += s1[i]; tl += s2[i]; }
        out[0] = 0.3f * (tg / 256.f) + 0.4f * (tl / 256.f);
    }
}

extern "C" void kernel_launch(void* const* d_in, const int* in_sizes, int n_in,
                              void* d_out, int out_size) {
    const float* vg   = (const float*)d_in[0];  // video_global [256,768]
    const float* tg   = (const float*)d_in[1];  // text_global  [256,768]
    const float* vl   = (const float*)d_in[2];  // video_local  [256,16,768]
    const float* tl   = (const float*)d_in[3];  // text_local   [256,32,768]
    const float* temp = (const float*)d_in[4];  // temp [1]
    float* out = (float*)d_out;

    k1_kernel<<<BB, 128>>>(vl, tl, temp);
    gemm_kernel<<<dim3(64, 2, SPLITK), 64>>>(vg, tg);
    lse_kernel<<<96, 256>>>(temp);
    final_kernel<<<1, 256>>>(out);
}